// round 11
// baseline (speedup 1.0000x reference)
#include <cuda_runtime.h>
#include <math.h>
#include <float.h>

#define BB 4
#define TT 1024
#define FF 1024
#define HH 16
#define DD 64
#define NR (BB*TT)        // 4096

// ---------------- scratch ----------------
__device__ float g_q[(size_t)NR * FF];
__device__ float g_k[(size_t)NR * FF];
__device__ float g_v[(size_t)NR * FF];
__device__ float g_x[(size_t)NR * FF];
__device__ int   g_mask_byte_mode;

// ---------------- helpers ----------------
// round-to-nearest tf32 operand: +0x1000 then HW truncates low 13 bits
__device__ __forceinline__ unsigned rnt(float x) {
    return __float_as_uint(x) + 0x1000u;
}
__device__ __forceinline__ void mma8(float c[4], const unsigned a[4], const unsigned b[2]) {
    asm("mma.sync.aligned.m16n8k8.row.col.f32.tf32.tf32.f32 "
        "{%0,%1,%2,%3},{%4,%5,%6,%7},{%8,%9},{%0,%1,%2,%3};"
        : "+f"(c[0]), "+f"(c[1]), "+f"(c[2]), "+f"(c[3])
        : "r"(a[0]), "r"(a[1]), "r"(a[2]), "r"(a[3]), "r"(b[0]), "r"(b[1]));
}
__device__ __forceinline__ unsigned sptr(const void* p) {
    return (unsigned)__cvta_generic_to_shared(p);
}
__device__ __forceinline__ void cpa16(unsigned s, const void* g) {
    asm volatile("cp.async.cg.shared.global [%0], [%1], 16;\n" :: "r"(s), "l"(g));
}
#define CPA_COMMIT() asm volatile("cp.async.commit_group;\n" ::)
#define CPA_WAIT(n)  asm volatile("cp.async.wait_group %0;\n" :: "n"(n))

// ---------------- mask dtype classifier ----------------
__global__ void detect_mask_kernel(const unsigned int* __restrict__ mask) {
    __shared__ int has_f, has_big;
    if (threadIdx.x == 0) { has_f = 0; has_big = 0; }
    __syncthreads();
    #pragma unroll
    for (int u = 0; u < 4; u++) {
        unsigned int w = mask[threadIdx.x * 4 + u];
        if (w == 0x3F800000u) atomicOr(&has_f, 1);
        else if (w > 1u)      atomicOr(&has_big, 1);
    }
    __syncthreads();
    if (threadIdx.x == 0)
        g_mask_byte_mode = (!has_f && has_big) ? 1 : 0;
}

// ============ QKV projections: 128x128 tile, 3-stage cp.async, single-pass tf32 (R9) ============
#define APAD 20
#define BPAD 136
#define NKT (FF / 16)       // 64

__global__ __launch_bounds__(256) void proj_tf32_kernel(
    const float* __restrict__ q_in, const float* __restrict__ k_in,
    const float* __restrict__ v_in,
    const float* __restrict__ Wq, const float* __restrict__ bq,
    const float* __restrict__ Wk, const float* __restrict__ bk,
    const float* __restrict__ Wv, const float* __restrict__ bv)
{
    const float *A, *W, *bias; float *C;
    if (blockIdx.z == 0)      { A = q_in; W = Wq; bias = bq; C = g_q; }
    else if (blockIdx.z == 1) { A = k_in; W = Wk; bias = bk; C = g_k; }
    else                      { A = v_in; W = Wv; bias = bv; C = g_v; }

    __shared__ float As[3][128][APAD];
    __shared__ float Bs[3][16][BPAD];

    int tid = threadIdx.x, lane = tid & 31, warp = tid >> 5;
    int wm = (warp >> 2) * 64, wn = (warp & 3) * 32;
    int bm = blockIdx.y * 128, bn = blockIdx.x * 128;

    int ar = tid >> 2, ac = (tid & 3) * 4;
    int br = tid >> 5, bc = (tid & 31) * 4;

    float acc[4][4][4];
    #pragma unroll
    for (int i = 0; i < 4; i++)
        #pragma unroll
        for (int j = 0; j < 4; j++)
            #pragma unroll
            for (int r = 0; r < 4; r++) acc[i][j][r] = 0.f;

    auto load_stage = [&](int s, int t) {
        int k0 = t * 16;
        cpa16(sptr(&As[s][ar][ac]),      A + (size_t)(bm + ar)      * FF + k0 + ac);
        cpa16(sptr(&As[s][ar + 64][ac]), A + (size_t)(bm + ar + 64) * FF + k0 + ac);
        cpa16(sptr(&Bs[s][br][bc]),      W + (size_t)(k0 + br)     * FF + bn + bc);
        cpa16(sptr(&Bs[s][br + 8][bc]),  W + (size_t)(k0 + br + 8) * FF + bn + bc);
        CPA_COMMIT();
    };

    load_stage(0, 0);
    load_stage(1, 1);

    for (int t = 0; t < NKT; t++) {
        if (t + 1 < NKT) { CPA_WAIT(1); } else { CPA_WAIT(0); }
        __syncthreads();
        if (t + 2 < NKT) load_stage((t + 2) % 3, t + 2);

        int s = t % 3;
        #pragma unroll
        for (int ks = 0; ks < 16; ks += 8) {
            unsigned ah[4][4], bh[4][2];
            #pragma unroll
            for (int mt = 0; mt < 4; mt++) {
                int r = wm + mt * 16 + (lane >> 2);
                int k = ks + (lane & 3);
                ah[mt][0] = rnt(As[s][r][k]);
                ah[mt][1] = rnt(As[s][r + 8][k]);
                ah[mt][2] = rnt(As[s][r][k + 4]);
                ah[mt][3] = rnt(As[s][r + 8][k + 4]);
            }
            #pragma unroll
            for (int nt = 0; nt < 4; nt++) {
                int k = ks + (lane & 3);
                int n = wn + nt * 8 + (lane >> 2);
                bh[nt][0] = rnt(Bs[s][k][n]);
                bh[nt][1] = rnt(Bs[s][k + 4][n]);
            }
            #pragma unroll
            for (int mt = 0; mt < 4; mt++)
                #pragma unroll
                for (int nt = 0; nt < 4; nt++)
                    mma8(acc[mt][nt], ah[mt], bh[nt]);
        }
    }

    #pragma unroll
    for (int mt = 0; mt < 4; mt++) {
        int r = bm + wm + mt * 16 + (lane >> 2);
        #pragma unroll
        for (int nt = 0; nt < 4; nt++) {
            int cc = bn + wn + nt * 8 + 2 * (lane & 3);
            float b0 = bias[cc], b1 = bias[cc + 1];
            float2 o0 = make_float2(acc[mt][nt][0] + b0, acc[mt][nt][1] + b1);
            float2 o1 = make_float2(acc[mt][nt][2] + b0, acc[mt][nt][3] + b1);
            *(float2*)(C + (size_t)r * FF + cc)       = o0;
            *(float2*)(C + (size_t)(r + 8) * FF + cc) = o1;
        }
    }
}

// ---------------- fused attention: single-pass tf32, K/V double-buffered via cp.async ----------------
#define EPAD 68
#define ATT_SMEM ((6 * 64 * EPAD + 128) * 4)
__global__ __launch_bounds__(256) void attn_fused_kernel(
    float* __restrict__ attn, const unsigned int* __restrict__ mask,
    const float* __restrict__ qmask)
{
    extern __shared__ float sm[];
    float* Qs   = sm;                      // 64*EPAD
    float* Kb   = Qs + 64 * EPAD;          // 2 * 64*EPAD
    float* Vb   = Kb + 2 * 64 * EPAD;      // 2 * 64*EPAD
    float* Es   = Vb + 2 * 64 * EPAD;      // 64*EPAD
    float* lsum = Es + 64 * EPAD;
    float* scs  = lsum + 64;

    int tid = threadIdx.x, lane = tid & 31, warp = tid >> 5;
    int hb = blockIdx.y, h = hb >> 2, b = hb & 3;
    int i0 = blockIdx.x * 64;
    int wm = (warp >> 2) * 32, wn = (warp & 3) * 16;
    int bytemode = g_mask_byte_mode;

    // per-thread KV cp.async mapping: 4 rows x 16B for K, same for V
    int kr = tid >> 2, kc = (tid & 3) * 16;   // row 0..63, col offset 0/16/32/48

    auto load_kv = [&](int buf, int j0) {
        float* Kd = Kb + buf * 64 * EPAD;
        float* Vd = Vb + buf * 64 * EPAD;
        const float* ksrc = g_k + (size_t)(b * TT + j0 + kr) * FF + h * DD + kc;
        const float* vsrc = g_v + (size_t)(b * TT + j0 + kr) * FF + h * DD + kc;
        cpa16(sptr(&Kd[kr * EPAD + kc]),      ksrc);
        cpa16(sptr(&Kd[kr * EPAD + kc + 4]),  ksrc + 4);
        cpa16(sptr(&Kd[kr * EPAD + kc + 8]),  ksrc + 8);
        cpa16(sptr(&Kd[kr * EPAD + kc + 12]), ksrc + 12);
        cpa16(sptr(&Vd[kr * EPAD + kc]),      vsrc);
        cpa16(sptr(&Vd[kr * EPAD + kc + 4]),  vsrc + 4);
        cpa16(sptr(&Vd[kr * EPAD + kc + 8]),  vsrc + 8);
        cpa16(sptr(&Vd[kr * EPAD + kc + 12]), vsrc + 12);
        CPA_COMMIT();
    };

    // Q tile raw (64x64)
    #pragma unroll
    for (int u = 0; u < 2; u++) {
        int s = tid + u * 256;
        int r = s >> 3, c4 = (s & 7) * 8;
        float4 q0 = *(const float4*)(g_q + (size_t)(b * TT + i0 + r) * FF + h * DD + c4);
        float4 q1 = *(const float4*)(g_q + (size_t)(b * TT + i0 + r) * FF + h * DD + c4 + 4);
        *(float4*)&Qs[r * EPAD + c4]     = q0;
        *(float4*)&Qs[r * EPAD + c4 + 4] = q1;
    }
    if (tid < 64) lsum[tid] = 0.f;

    load_kv(0, 0);

    float X[2][2][4];
    #pragma unroll
    for (int i = 0; i < 2; i++)
        #pragma unroll
        for (int j = 0; j < 2; j++)
            #pragma unroll
            for (int r = 0; r < 4; r++) X[i][j][r] = 0.f;

    __syncthreads();

    for (int jt = 0; jt < 16; jt++) {
        int j0 = jt * 64;
        int cur = jt & 1;
        float* Ks = Kb + cur * 64 * EPAD;
        float* Vs = Vb + cur * 64 * EPAD;

        CPA_WAIT(0);
        __syncthreads();
        if (jt + 1 < 16) load_kv((jt + 1) & 1, j0 + 64);

        float sacc[2][2][4];
        #pragma unroll
        for (int i = 0; i < 2; i++)
            #pragma unroll
            for (int j = 0; j < 2; j++)
                #pragma unroll
                for (int r = 0; r < 4; r++) sacc[i][j][r] = 0.f;

        #pragma unroll
        for (int ks = 0; ks < 64; ks += 8) {
            unsigned ah[2][4], bh[2][2];
            #pragma unroll
            for (int mt = 0; mt < 2; mt++) {
                int r = wm + mt * 16 + (lane >> 2);
                int k = ks + (lane & 3);
                ah[mt][0] = rnt(Qs[r * EPAD + k]);
                ah[mt][1] = rnt(Qs[(r + 8) * EPAD + k]);
                ah[mt][2] = rnt(Qs[r * EPAD + k + 4]);
                ah[mt][3] = rnt(Qs[(r + 8) * EPAD + k + 4]);
            }
            #pragma unroll
            for (int nt = 0; nt < 2; nt++) {
                int n = wn + nt * 8 + (lane >> 2);
                int k = ks + (lane & 3);
                bh[nt][0] = rnt(Ks[n * EPAD + k]);
                bh[nt][1] = rnt(Ks[n * EPAD + k + 4]);
            }
            #pragma unroll
            for (int mt = 0; mt < 2; mt++)
                #pragma unroll
                for (int nt = 0; nt < 2; nt++)
                    mma8(sacc[mt][nt], ah[mt], bh[nt]);
        }

        // mask + exp -> attn (unnormalized) and Es
        #pragma unroll
        for (int mt = 0; mt < 2; mt++) {
            #pragma unroll
            for (int nt = 0; nt < 2; nt++) {
                int ri = wm + mt * 16 + (lane >> 2);
                int cj = wn + nt * 8 + 2 * (lane & 3);
                size_t gi0 = ((size_t)hb * TT + i0 + ri) * TT + j0 + cj;
                size_t gi1 = gi0 + (size_t)8 * TT;
                unsigned m00, m01, m10, m11;
                if (bytemode) {
                    const unsigned char* mb = (const unsigned char*)mask;
                    m00 = mb[gi0]; m01 = mb[gi0 + 1];
                    m10 = mb[gi1]; m11 = mb[gi1 + 1];
                } else {
                    m00 = mask[gi0]; m01 = mask[gi0 + 1];
                    m10 = mask[gi1]; m11 = mask[gi1 + 1];
                }
                float e00 = m00 ? 0.f : __expf(sacc[mt][nt][0] * 0.125f);
                float e01 = m01 ? 0.f : __expf(sacc[mt][nt][1] * 0.125f);
                float e10 = m10 ? 0.f : __expf(sacc[mt][nt][2] * 0.125f);
                float e11 = m11 ? 0.f : __expf(sacc[mt][nt][3] * 0.125f);
                *(float2*)(attn + gi0) = make_float2(e00, e01);
                *(float2*)(attn + gi1) = make_float2(e10, e11);
                Es[ri * EPAD + cj]           = e00;
                Es[ri * EPAD + cj + 1]       = e01;
                Es[(ri + 8) * EPAD + cj]     = e10;
                Es[(ri + 8) * EPAD + cj + 1] = e11;
            }
        }
        __syncthreads();

        // row sums
        {
            int r = tid >> 2, seg = (tid & 3) * 16;
            float p = 0.f;
            #pragma unroll
            for (int t = 0; t < 16; t++) p += Es[r * EPAD + seg + t];
            p += __shfl_xor_sync(0xFFFFFFFFu, p, 1);
            p += __shfl_xor_sync(0xFFFFFFFFu, p, 2);
            if ((tid & 3) == 0) lsum[r] += p;
        }

        // X += E @ V
        #pragma unroll
        for (int ks = 0; ks < 64; ks += 8) {
            unsigned ae[2][4], bv[2][2];
            #pragma unroll
            for (int mt = 0; mt < 2; mt++) {
                int r = wm + mt * 16 + (lane >> 2);
                int k = ks + (lane & 3);
                ae[mt][0] = rnt(Es[r * EPAD + k]);
                ae[mt][1] = rnt(Es[(r + 8) * EPAD + k]);
                ae[mt][2] = rnt(Es[r * EPAD + k + 4]);
                ae[mt][3] = rnt(Es[(r + 8) * EPAD + k + 4]);
            }
            #pragma unroll
            for (int nt = 0; nt < 2; nt++) {
                int n = wn + nt * 8 + (lane >> 2);
                int k = ks + (lane & 3);
                bv[nt][0] = rnt(Vs[k * EPAD + n]);
                bv[nt][1] = rnt(Vs[(k + 4) * EPAD + n]);
            }
            #pragma unroll
            for (int mt = 0; mt < 2; mt++)
                #pragma unroll
                for (int nt = 0; nt < 2; nt++)
                    mma8(X[mt][nt], ae[mt], bv[nt]);
        }
        __syncthreads();
    }

    if (tid < 64) scs[tid] = qmask[b * TT + i0 + tid] / lsum[tid];
    __syncthreads();

    #pragma unroll
    for (int mt = 0; mt < 2; mt++) {
        int ri = wm + mt * 16 + (lane >> 2);
        float sc0 = scs[ri];
        float sc1 = scs[ri + 8];
        #pragma unroll
        for (int nt = 0; nt < 2; nt++) {
            int d = wn + nt * 8 + 2 * (lane & 3);
            float2 o0 = make_float2(X[mt][nt][0] * sc0, X[mt][nt][1] * sc0);
            float2 o1 = make_float2(X[mt][nt][2] * sc1, X[mt][nt][3] * sc1);
            *(float2*)(g_x + (size_t)(b * TT + i0 + ri) * FF + h * DD + d)     = o0;
            *(float2*)(g_x + (size_t)(b * TT + i0 + ri + 8) * FF + h * DD + d) = o1;
        }
    }

    // normalize the CTA's own attn block in place (L2-hot)
    for (int u = 0; u < 64; u++) {
        int s = tid + u * 256;
        int r = s >> 8, c4 = (s & 255) << 2;
        float sc = scs[r];
        float4* p = (float4*)(attn + ((size_t)hb * TT + i0 + r) * TT + c4);
        float4 v = *p;
        v.x *= sc; v.y *= sc; v.z *= sc; v.w *= sc;
        *p = v;
    }
}

// ============ final: 128x128 tile, 3-stage cp.async, single tf32 (R9) ============
#define FNKT (2 * FF / 16)    // 128
__global__ __launch_bounds__(256) void final_tf32_kernel(
    const float* __restrict__ query, const float* __restrict__ Wf,
    const float* __restrict__ bf, float* __restrict__ out)
{
    __shared__ float As[3][128][APAD];
    __shared__ float Bs[3][16][BPAD];

    int tid = threadIdx.x, lane = tid & 31, warp = tid >> 5;
    int wm = (warp >> 2) * 64, wn = (warp & 3) * 32;
    int bm = blockIdx.y * 128, bn = blockIdx.x * 128;

    int ar = tid >> 2, ac = (tid & 3) * 4;
    int br = tid >> 5, bc = (tid & 31) * 4;

    float acc[4][4][4];
    #pragma unroll
    for (int i = 0; i < 4; i++)
        #pragma unroll
        for (int j = 0; j < 4; j++)
            #pragma unroll
            for (int r = 0; r < 4; r++) acc[i][j][r] = 0.f;

    auto load_stage = [&](int s, int t) {
        int k0 = t * 16;
        const float* a_base;
        int koff;
        if (k0 < FF) { a_base = g_x;   koff = k0; }
        else         { a_base = query; koff = k0 - FF; }
        cpa16(sptr(&As[s][ar][ac]),      a_base + (size_t)(bm + ar)      * FF + koff + ac);
        cpa16(sptr(&As[s][ar + 64][ac]), a_base + (size_t)(bm + ar + 64) * FF + koff + ac);
        cpa16(sptr(&Bs[s][br][bc]),      Wf + (size_t)(k0 + br)     * FF + bn + bc);
        cpa16(sptr(&Bs[s][br + 8][bc]),  Wf + (size_t)(k0 + br + 8) * FF + bn + bc);
        CPA_COMMIT();
    };

    load_stage(0, 0);
    load_stage(1, 1);

    for (int t = 0; t < FNKT; t++) {
        if (t + 1 < FNKT) { CPA_WAIT(1); } else { CPA_WAIT(0); }
        __syncthreads();
        if (t + 2 < FNKT) load_stage((t + 2) % 3, t + 2);

        int s = t % 3;
        #pragma unroll
        for (int ks = 0; ks < 16; ks += 8) {
            unsigned ah[4][4], bh[4][2];
            #pragma unroll
            for (int mt = 0; mt < 4; mt++) {
                int r = wm + mt * 16 + (lane >> 2);
                int k = ks + (lane & 3);
                ah[mt][0] = rnt(As[s][r][k]);
                ah[mt][1] = rnt(As[s][r + 8][k]);
                ah[mt][2] = rnt(As[s][r][k + 4]);
                ah[mt][3] = rnt(As[s][r + 8][k + 4]);
            }
            #pragma unroll
            for (int nt = 0; nt < 4; nt++) {
                int k = ks + (lane & 3);
                int n = wn + nt * 8 + (lane >> 2);
                bh[nt][0] = rnt(Bs[s][k][n]);
                bh[nt][1] = rnt(Bs[s][k + 4][n]);
            }
            #pragma unroll
            for (int mt = 0; mt < 4; mt++)
                #pragma unroll
                for (int nt = 0; nt < 4; nt++)
                    mma8(acc[mt][nt], ah[mt], bh[nt]);
        }
    }

    #pragma unroll
    for (int mt = 0; mt < 4; mt++) {
        int r = bm + wm + mt * 16 + (lane >> 2);
        #pragma unroll
        for (int nt = 0; nt < 4; nt++) {
            int cc = bn + wn + nt * 8 + 2 * (lane & 3);
            float b0 = bf[cc], b1 = bf[cc + 1];
            const float* q0 = query + (size_t)r * FF + cc;
            const float* q1 = query + (size_t)(r + 8) * FF + cc;
            float2 o0 = make_float2(acc[mt][nt][0] + b0 + q0[0],
                                    acc[mt][nt][1] + b1 + q0[1]);
            float2 o1 = make_float2(acc[mt][nt][2] + b0 + q1[0],
                                    acc[mt][nt][3] + b1 + q1[1]);
            *(float2*)(out + (size_t)r * FF + cc)       = o0;
            *(float2*)(out + (size_t)(r + 8) * FF + cc) = o1;
        }
    }
}

// ---------------- launch ----------------
extern "C" void kernel_launch(void* const* d_in, const int* in_sizes, int n_in,
                              void* d_out, int out_size)
{
    const float* query = (const float*)d_in[0];
    const float* key   = (const float*)d_in[1];
    const float* value = (const float*)d_in[2];
    const unsigned int* mask = (const unsigned int*)d_in[3];
    const float* qmask = (const float*)d_in[4];
    const float* Wq = (const float*)d_in[5];
    const float* bq = (const float*)d_in[6];
    const float* Wk = (const float*)d_in[7];
    const float* bk = (const float*)d_in[8];
    const float* Wv = (const float*)d_in[9];
    const float* bv = (const float*)d_in[10];
    const float* Wf = (const float*)d_in[11];
    const float* bf = (const float*)d_in[12];

    float* out  = (float*)d_out;
    float* attn = out + (size_t)NR * FF;

    cudaFuncSetAttribute(attn_fused_kernel,
                         cudaFuncAttributeMaxDynamicSharedMemorySize, ATT_SMEM);

    detect_mask_kernel<<<1, 256>>>(mask);
    proj_tf32_kernel<<<dim3(8, 32, 3), 256>>>(query, key, value, Wq, bq, Wk, bk, Wv, bv);
    attn_fused_kernel<<<dim3(16, 64), 256, ATT_SMEM>>>(attn, mask, qmask);
    final_tf32_kernel<<<dim3(8, 32), 256>>>(query, Wf, bf, out);
}

// round 12
// speedup vs baseline: 1.0418x; 1.0418x over previous
#include <cuda_runtime.h>
#include <math.h>
#include <float.h>

#define BB 4
#define TT 1024
#define FF 1024
#define HH 16
#define DD 64
#define NR (BB*TT)        // 4096

// ---------------- scratch ----------------
__device__ float g_q[(size_t)NR * FF];
__device__ float g_k[(size_t)NR * FF];
__device__ float g_v[(size_t)NR * FF];
__device__ float g_x[(size_t)NR * FF];
__device__ int   g_mask_byte_mode;

// ---------------- helpers ----------------
// round-to-nearest tf32 operand: +0x1000 then HW truncates low 13 bits
__device__ __forceinline__ unsigned rnt(float x) {
    return __float_as_uint(x) + 0x1000u;
}
// explicit RN round to tf32, stored as f32 (producer-side pre-round)
__device__ __forceinline__ float tfr(float x) {
    unsigned u = (__float_as_uint(x) + 0x1000u) & 0xFFFFE000u;
    return __uint_as_float(u);
}
__device__ __forceinline__ void mma8(float c[4], const unsigned a[4], const unsigned b[2]) {
    asm("mma.sync.aligned.m16n8k8.row.col.f32.tf32.tf32.f32 "
        "{%0,%1,%2,%3},{%4,%5,%6,%7},{%8,%9},{%0,%1,%2,%3};"
        : "+f"(c[0]), "+f"(c[1]), "+f"(c[2]), "+f"(c[3])
        : "r"(a[0]), "r"(a[1]), "r"(a[2]), "r"(a[3]), "r"(b[0]), "r"(b[1]));
}
__device__ __forceinline__ unsigned sptr(const void* p) {
    return (unsigned)__cvta_generic_to_shared(p);
}
__device__ __forceinline__ void cpa16(unsigned s, const void* g) {
    asm volatile("cp.async.cg.shared.global [%0], [%1], 16;\n" :: "r"(s), "l"(g));
}
#define CPA_COMMIT() asm volatile("cp.async.commit_group;\n" ::)
#define CPA_WAIT(n)  asm volatile("cp.async.wait_group %0;\n" :: "n"(n))

// ---------------- mask dtype classifier ----------------
__global__ void detect_mask_kernel(const unsigned int* __restrict__ mask) {
    __shared__ int has_f, has_big;
    if (threadIdx.x == 0) { has_f = 0; has_big = 0; }
    __syncthreads();
    #pragma unroll
    for (int u = 0; u < 4; u++) {
        unsigned int w = mask[threadIdx.x * 4 + u];
        if (w == 0x3F800000u) atomicOr(&has_f, 1);
        else if (w > 1u)      atomicOr(&has_big, 1);
    }
    __syncthreads();
    if (threadIdx.x == 0)
        g_mask_byte_mode = (!has_f && has_big) ? 1 : 0;
}

// ============ QKV projections: 128x128 tile, 3-stage cp.async, single-pass tf32 ============
// outputs pre-rounded to tf32 (consumer rounds anyway -> bitwise identical downstream)
#define APAD 20
#define BPAD 136
#define NKT (FF / 16)       // 64

__global__ __launch_bounds__(256) void proj_tf32_kernel(
    const float* __restrict__ q_in, const float* __restrict__ k_in,
    const float* __restrict__ v_in,
    const float* __restrict__ Wq, const float* __restrict__ bq,
    const float* __restrict__ Wk, const float* __restrict__ bk,
    const float* __restrict__ Wv, const float* __restrict__ bv)
{
    const float *A, *W, *bias; float *C;
    if (blockIdx.z == 0)      { A = q_in; W = Wq; bias = bq; C = g_q; }
    else if (blockIdx.z == 1) { A = k_in; W = Wk; bias = bk; C = g_k; }
    else                      { A = v_in; W = Wv; bias = bv; C = g_v; }

    __shared__ float As[3][128][APAD];
    __shared__ float Bs[3][16][BPAD];

    int tid = threadIdx.x, lane = tid & 31, warp = tid >> 5;
    int wm = (warp >> 2) * 64, wn = (warp & 3) * 32;
    int bm = blockIdx.y * 128, bn = blockIdx.x * 128;

    int ar = tid >> 2, ac = (tid & 3) * 4;
    int br = tid >> 5, bc = (tid & 31) * 4;

    float acc[4][4][4];
    #pragma unroll
    for (int i = 0; i < 4; i++)
        #pragma unroll
        for (int j = 0; j < 4; j++)
            #pragma unroll
            for (int r = 0; r < 4; r++) acc[i][j][r] = 0.f;

    auto load_stage = [&](int s, int t) {
        int k0 = t * 16;
        cpa16(sptr(&As[s][ar][ac]),      A + (size_t)(bm + ar)      * FF + k0 + ac);
        cpa16(sptr(&As[s][ar + 64][ac]), A + (size_t)(bm + ar + 64) * FF + k0 + ac);
        cpa16(sptr(&Bs[s][br][bc]),      W + (size_t)(k0 + br)     * FF + bn + bc);
        cpa16(sptr(&Bs[s][br + 8][bc]),  W + (size_t)(k0 + br + 8) * FF + bn + bc);
        CPA_COMMIT();
    };

    load_stage(0, 0);
    load_stage(1, 1);

    for (int t = 0; t < NKT; t++) {
        if (t + 1 < NKT) { CPA_WAIT(1); } else { CPA_WAIT(0); }
        __syncthreads();
        if (t + 2 < NKT) load_stage((t + 2) % 3, t + 2);

        int s = t % 3;
        #pragma unroll
        for (int ks = 0; ks < 16; ks += 8) {
            unsigned ah[4][4], bh[4][2];
            #pragma unroll
            for (int mt = 0; mt < 4; mt++) {
                int r = wm + mt * 16 + (lane >> 2);
                int k = ks + (lane & 3);
                ah[mt][0] = rnt(As[s][r][k]);
                ah[mt][1] = rnt(As[s][r + 8][k]);
                ah[mt][2] = rnt(As[s][r][k + 4]);
                ah[mt][3] = rnt(As[s][r + 8][k + 4]);
            }
            #pragma unroll
            for (int nt = 0; nt < 4; nt++) {
                int k = ks + (lane & 3);
                int n = wn + nt * 8 + (lane >> 2);
                bh[nt][0] = rnt(Bs[s][k][n]);
                bh[nt][1] = rnt(Bs[s][k + 4][n]);
            }
            #pragma unroll
            for (int mt = 0; mt < 4; mt++)
                #pragma unroll
                for (int nt = 0; nt < 4; nt++)
                    mma8(acc[mt][nt], ah[mt], bh[nt]);
        }
    }

    #pragma unroll
    for (int mt = 0; mt < 4; mt++) {
        int r = bm + wm + mt * 16 + (lane >> 2);
        #pragma unroll
        for (int nt = 0; nt < 4; nt++) {
            int cc = bn + wn + nt * 8 + 2 * (lane & 3);
            float b0 = bias[cc], b1 = bias[cc + 1];
            float2 o0 = make_float2(tfr(acc[mt][nt][0] + b0), tfr(acc[mt][nt][1] + b1));
            float2 o1 = make_float2(tfr(acc[mt][nt][2] + b0), tfr(acc[mt][nt][3] + b1));
            *(float2*)(C + (size_t)r * FF + cc)       = o0;
            *(float2*)(C + (size_t)(r + 8) * FF + cc) = o1;
        }
    }
}

// ---------------- fused attention: inputs pre-rounded (no IADD on Q/K/V frags),
//                  coalesced attn writes, vector mask loads ----------------
#define EPAD 68
#define ATT_SMEM ((4 * 64 * EPAD + 128) * 4)
__global__ __launch_bounds__(256) void attn_fused_kernel(
    float* __restrict__ attn, const unsigned int* __restrict__ mask,
    const float* __restrict__ qmask)
{
    extern __shared__ float sm[];
    float* Qs   = sm;
    float* Ks   = Qs + 64 * EPAD;
    float* Vs   = Ks + 64 * EPAD;
    float* Es   = Vs + 64 * EPAD;
    float* lsum = Es + 64 * EPAD;
    float* scs  = lsum + 64;

    int tid = threadIdx.x, lane = tid & 31, warp = tid >> 5;
    int hb = blockIdx.y, h = hb >> 2, b = hb & 3;
    int i0 = blockIdx.x * 64;
    int wm = (warp >> 2) * 32, wn = (warp & 3) * 16;
    int bytemode = g_mask_byte_mode;

    // Q tile (pre-rounded in gmem)
    #pragma unroll
    for (int u = 0; u < 2; u++) {
        int s = tid + u * 256;
        int r = s >> 3, c4 = (s & 7) * 8;
        float4 q0 = *(const float4*)(g_q + (size_t)(b * TT + i0 + r) * FF + h * DD + c4);
        float4 q1 = *(const float4*)(g_q + (size_t)(b * TT + i0 + r) * FF + h * DD + c4 + 4);
        *(float4*)&Qs[r * EPAD + c4]     = q0;
        *(float4*)&Qs[r * EPAD + c4 + 4] = q1;
    }
    if (tid < 64) lsum[tid] = 0.f;

    float X[2][2][4];
    #pragma unroll
    for (int i = 0; i < 2; i++)
        #pragma unroll
        for (int j = 0; j < 2; j++)
            #pragma unroll
            for (int r = 0; r < 4; r++) X[i][j][r] = 0.f;

    __syncthreads();

    for (int j0 = 0; j0 < TT; j0 += 64) {
        #pragma unroll
        for (int u = 0; u < 2; u++) {
            int s = tid + u * 256;
            int r = s >> 3, c4 = (s & 7) * 8;
            float4 k0 = *(const float4*)(g_k + (size_t)(b * TT + j0 + r) * FF + h * DD + c4);
            float4 k1 = *(const float4*)(g_k + (size_t)(b * TT + j0 + r) * FF + h * DD + c4 + 4);
            *(float4*)&Ks[r * EPAD + c4]     = k0;
            *(float4*)&Ks[r * EPAD + c4 + 4] = k1;
            float4 v0 = *(const float4*)(g_v + (size_t)(b * TT + j0 + r) * FF + h * DD + c4);
            float4 v1 = *(const float4*)(g_v + (size_t)(b * TT + j0 + r) * FF + h * DD + c4 + 4);
            *(float4*)&Vs[r * EPAD + c4]     = v0;
            *(float4*)&Vs[r * EPAD + c4 + 4] = v1;
        }
        __syncthreads();

        float sacc[2][2][4];
        #pragma unroll
        for (int i = 0; i < 2; i++)
            #pragma unroll
            for (int j = 0; j < 2; j++)
                #pragma unroll
                for (int r = 0; r < 4; r++) sacc[i][j][r] = 0.f;

        #pragma unroll
        for (int ks = 0; ks < 64; ks += 8) {
            unsigned ah[2][4], bh[2][2];
            #pragma unroll
            for (int mt = 0; mt < 2; mt++) {
                int r = wm + mt * 16 + (lane >> 2);
                int k = ks + (lane & 3);
                ah[mt][0] = __float_as_uint(Qs[r * EPAD + k]);
                ah[mt][1] = __float_as_uint(Qs[(r + 8) * EPAD + k]);
                ah[mt][2] = __float_as_uint(Qs[r * EPAD + k + 4]);
                ah[mt][3] = __float_as_uint(Qs[(r + 8) * EPAD + k + 4]);
            }
            #pragma unroll
            for (int nt = 0; nt < 2; nt++) {
                int n = wn + nt * 8 + (lane >> 2);
                int k = ks + (lane & 3);
                bh[nt][0] = __float_as_uint(Ks[n * EPAD + k]);
                bh[nt][1] = __float_as_uint(Ks[n * EPAD + k + 4]);
            }
            #pragma unroll
            for (int mt = 0; mt < 2; mt++)
                #pragma unroll
                for (int nt = 0; nt < 2; nt++)
                    mma8(sacc[mt][nt], ah[mt], bh[nt]);
        }

        // mask + exp -> Es (smem only; gmem write deferred to coalesced copy)
        #pragma unroll
        for (int mt = 0; mt < 2; mt++) {
            #pragma unroll
            for (int nt = 0; nt < 2; nt++) {
                int ri = wm + mt * 16 + (lane >> 2);
                int cj = wn + nt * 8 + 2 * (lane & 3);
                size_t gi0 = ((size_t)hb * TT + i0 + ri) * TT + j0 + cj;
                size_t gi1 = gi0 + (size_t)8 * TT;
                unsigned m00, m01, m10, m11;
                if (bytemode) {
                    const unsigned char* mb = (const unsigned char*)mask;
                    uchar2 c0 = *(const uchar2*)(mb + gi0);
                    uchar2 c1 = *(const uchar2*)(mb + gi1);
                    m00 = c0.x; m01 = c0.y; m10 = c1.x; m11 = c1.y;
                } else {
                    uint2 w0 = *(const uint2*)(mask + gi0);
                    uint2 w1 = *(const uint2*)(mask + gi1);
                    m00 = w0.x; m01 = w0.y; m10 = w1.x; m11 = w1.y;
                }
                Es[ri * EPAD + cj]           = m00 ? 0.f : __expf(sacc[mt][nt][0] * 0.125f);
                Es[ri * EPAD + cj + 1]       = m01 ? 0.f : __expf(sacc[mt][nt][1] * 0.125f);
                Es[(ri + 8) * EPAD + cj]     = m10 ? 0.f : __expf(sacc[mt][nt][2] * 0.125f);
                Es[(ri + 8) * EPAD + cj + 1] = m11 ? 0.f : __expf(sacc[mt][nt][3] * 0.125f);
            }
        }
        __syncthreads();

        // coalesced unnormalized attn write from Es
        #pragma unroll
        for (int u = 0; u < 4; u++) {
            int s2 = tid + u * 256;
            int r = s2 >> 4, c4 = (s2 & 15) * 4;
            *(float4*)(attn + ((size_t)hb * TT + i0 + r) * TT + j0 + c4) =
                *(const float4*)&Es[r * EPAD + c4];
        }

        // row sums
        {
            int r = tid >> 2, seg = (tid & 3) * 16;
            float p = 0.f;
            #pragma unroll
            for (int t = 0; t < 16; t++) p += Es[r * EPAD + seg + t];
            p += __shfl_xor_sync(0xFFFFFFFFu, p, 1);
            p += __shfl_xor_sync(0xFFFFFFFFu, p, 2);
            if ((tid & 3) == 0) lsum[r] += p;
        }

        // X += E @ V  (E needs rounding; V pre-rounded)
        #pragma unroll
        for (int ks = 0; ks < 64; ks += 8) {
            unsigned ae[2][4], bv[2][2];
            #pragma unroll
            for (int mt = 0; mt < 2; mt++) {
                int r = wm + mt * 16 + (lane >> 2);
                int k = ks + (lane & 3);
                ae[mt][0] = rnt(Es[r * EPAD + k]);
                ae[mt][1] = rnt(Es[(r + 8) * EPAD + k]);
                ae[mt][2] = rnt(Es[r * EPAD + k + 4]);
                ae[mt][3] = rnt(Es[(r + 8) * EPAD + k + 4]);
            }
            #pragma unroll
            for (int nt = 0; nt < 2; nt++) {
                int n = wn + nt * 8 + (lane >> 2);
                int k = ks + (lane & 3);
                bv[nt][0] = __float_as_uint(Vs[k * EPAD + n]);
                bv[nt][1] = __float_as_uint(Vs[(k + 4) * EPAD + n]);
            }
            #pragma unroll
            for (int mt = 0; mt < 2; mt++)
                #pragma unroll
                for (int nt = 0; nt < 2; nt++)
                    mma8(X[mt][nt], ae[mt], bv[nt]);
        }
        __syncthreads();
    }

    if (tid < 64) scs[tid] = qmask[b * TT + i0 + tid] / lsum[tid];
    __syncthreads();

    // x epilogue: pre-round to tf32 (final rounds anyway -> bitwise identical)
    #pragma unroll
    for (int mt = 0; mt < 2; mt++) {
        int ri = wm + mt * 16 + (lane >> 2);
        float sc0 = scs[ri];
        float sc1 = scs[ri + 8];
        #pragma unroll
        for (int nt = 0; nt < 2; nt++) {
            int d = wn + nt * 8 + 2 * (lane & 3);
            float2 o0 = make_float2(tfr(X[mt][nt][0] * sc0), tfr(X[mt][nt][1] * sc0));
            float2 o1 = make_float2(tfr(X[mt][nt][2] * sc1), tfr(X[mt][nt][3] * sc1));
            *(float2*)(g_x + (size_t)(b * TT + i0 + ri) * FF + h * DD + d)     = o0;
            *(float2*)(g_x + (size_t)(b * TT + i0 + ri + 8) * FF + h * DD + d) = o1;
        }
    }

    // normalize the CTA's own attn block in place (L2-hot)
    for (int u = 0; u < 64; u++) {
        int s = tid + u * 256;
        int r = s >> 8, c4 = (s & 255) << 2;
        float sc = scs[r];
        float4* p = (float4*)(attn + ((size_t)hb * TT + i0 + r) * TT + c4);
        float4 v = *p;
        v.x *= sc; v.y *= sc; v.z *= sc; v.w *= sc;
        *p = v;
    }
}

// ============ final: 128x128 tile, 3-stage cp.async; g_x half needs no rnt ============
#define FNKT (2 * FF / 16)    // 128
__global__ __launch_bounds__(256) void final_tf32_kernel(
    const float* __restrict__ query, const float* __restrict__ Wf,
    const float* __restrict__ bf, float* __restrict__ out)
{
    __shared__ float As[3][128][APAD];
    __shared__ float Bs[3][16][BPAD];

    int tid = threadIdx.x, lane = tid & 31, warp = tid >> 5;
    int wm = (warp >> 2) * 64, wn = (warp & 3) * 32;
    int bm = blockIdx.y * 128, bn = blockIdx.x * 128;

    int ar = tid >> 2, ac = (tid & 3) * 4;
    int br = tid >> 5, bc = (tid & 31) * 4;

    float acc[4][4][4];
    #pragma unroll
    for (int i = 0; i < 4; i++)
        #pragma unroll
        for (int j = 0; j < 4; j++)
            #pragma unroll
            for (int r = 0; r < 4; r++) acc[i][j][r] = 0.f;

    auto load_stage = [&](int s, int t) {
        int k0 = t * 16;
        const float* a_base;
        int koff;
        if (k0 < FF) { a_base = g_x;   koff = k0; }
        else         { a_base = query; koff = k0 - FF; }
        cpa16(sptr(&As[s][ar][ac]),      a_base + (size_t)(bm + ar)      * FF + koff + ac);
        cpa16(sptr(&As[s][ar + 64][ac]), a_base + (size_t)(bm + ar + 64) * FF + koff + ac);
        cpa16(sptr(&Bs[s][br][bc]),      Wf + (size_t)(k0 + br)     * FF + bn + bc);
        cpa16(sptr(&Bs[s][br + 8][bc]),  Wf + (size_t)(k0 + br + 8) * FF + bn + bc);
        CPA_COMMIT();
    };

    load_stage(0, 0);
    load_stage(1, 1);

    for (int t = 0; t < FNKT; t++) {
        if (t + 1 < FNKT) { CPA_WAIT(1); } else { CPA_WAIT(0); }
        __syncthreads();
        if (t + 2 < FNKT) load_stage((t + 2) % 3, t + 2);

        int s = t % 3;
        bool araw = (t < 64);    // g_x half pre-rounded
        #pragma unroll
        for (int ks = 0; ks < 16; ks += 8) {
            unsigned ah[4][4], bh[4][2];
            if (araw) {
                #pragma unroll
                for (int mt = 0; mt < 4; mt++) {
                    int r = wm + mt * 16 + (lane >> 2);
                    int k = ks + (lane & 3);
                    ah[mt][0] = __float_as_uint(As[s][r][k]);
                    ah[mt][1] = __float_as_uint(As[s][r + 8][k]);
                    ah[mt][2] = __float_as_uint(As[s][r][k + 4]);
                    ah[mt][3] = __float_as_uint(As[s][r + 8][k + 4]);
                }
            } else {
                #pragma unroll
                for (int mt = 0; mt < 4; mt++) {
                    int r = wm + mt * 16 + (lane >> 2);
                    int k = ks + (lane & 3);
                    ah[mt][0] = rnt(As[s][r][k]);
                    ah[mt][1] = rnt(As[s][r + 8][k]);
                    ah[mt][2] = rnt(As[s][r][k + 4]);
                    ah[mt][3] = rnt(As[s][r + 8][k + 4]);
                }
            }
            #pragma unroll
            for (int nt = 0; nt < 4; nt++) {
                int k = ks + (lane & 3);
                int n = wn + nt * 8 + (lane >> 2);
                bh[nt][0] = rnt(Bs[s][k][n]);
                bh[nt][1] = rnt(Bs[s][k + 4][n]);
            }
            #pragma unroll
            for (int mt = 0; mt < 4; mt++)
                #pragma unroll
                for (int nt = 0; nt < 4; nt++)
                    mma8(acc[mt][nt], ah[mt], bh[nt]);
        }
    }

    #pragma unroll
    for (int mt = 0; mt < 4; mt++) {
        int r = bm + wm + mt * 16 + (lane >> 2);
        #pragma unroll
        for (int nt = 0; nt < 4; nt++) {
            int cc = bn + wn + nt * 8 + 2 * (lane & 3);
            float b0 = bf[cc], b1 = bf[cc + 1];
            const float* q0 = query + (size_t)r * FF + cc;
            const float* q1 = query + (size_t)(r + 8) * FF + cc;
            float2 o0 = make_float2(acc[mt][nt][0] + b0 + q0[0],
                                    acc[mt][nt][1] + b1 + q0[1]);
            float2 o1 = make_float2(acc[mt][nt][2] + b0 + q1[0],
                                    acc[mt][nt][3] + b1 + q1[1]);
            *(float2*)(out + (size_t)r * FF + cc)       = o0;
            *(float2*)(out + (size_t)(r + 8) * FF + cc) = o1;
        }
    }
}

// ---------------- launch ----------------
extern "C" void kernel_launch(void* const* d_in, const int* in_sizes, int n_in,
                              void* d_out, int out_size)
{
    const float* query = (const float*)d_in[0];
    const float* key   = (const float*)d_in[1];
    const float* value = (const float*)d_in[2];
    const unsigned int* mask = (const unsigned int*)d_in[3];
    const float* qmask = (const float*)d_in[4];
    const float* Wq = (const float*)d_in[5];
    const float* bq = (const float*)d_in[6];
    const float* Wk = (const float*)d_in[7];
    const float* bk = (const float*)d_in[8];
    const float* Wv = (const float*)d_in[9];
    const float* bv = (const float*)d_in[10];
    const float* Wf = (const float*)d_in[11];
    const float* bf = (const float*)d_in[12];

    float* out  = (float*)d_out;
    float* attn = out + (size_t)NR * FF;

    cudaFuncSetAttribute(attn_fused_kernel,
                         cudaFuncAttributeMaxDynamicSharedMemorySize, ATT_SMEM);

    detect_mask_kernel<<<1, 256>>>(mask);
    proj_tf32_kernel<<<dim3(8, 32, 3), 256>>>(query, key, value, Wq, bq, Wk, bk, Wv, bv);
    attn_fused_kernel<<<dim3(16, 64), 256, ATT_SMEM>>>(attn, mask, qmask);
    final_tf32_kernel<<<dim3(8, 32), 256>>>(query, Wf, bf, out);
}

// round 13
// speedup vs baseline: 1.0661x; 1.0233x over previous
#include <cuda_runtime.h>
#include <math.h>
#include <float.h>

#define BB 4
#define TT 1024
#define FF 1024
#define HH 16
#define DD 64
#define NR (BB*TT)        // 4096

// ---------------- scratch ----------------
__device__ float g_q[(size_t)NR * FF];
__device__ float g_k[(size_t)NR * FF];
__device__ float g_v[(size_t)NR * FF];
__device__ float g_x[(size_t)NR * FF];
__device__ int   g_mask_byte_mode;

// ---------------- helpers ----------------
// round-to-nearest tf32 operand: +0x1000 then HW truncates low 13 bits
__device__ __forceinline__ unsigned rnt(float x) {
    return __float_as_uint(x) + 0x1000u;
}
// explicit RN round to tf32, stored as f32 (producer-side pre-round)
__device__ __forceinline__ float tfr(float x) {
    unsigned u = (__float_as_uint(x) + 0x1000u) & 0xFFFFE000u;
    return __uint_as_float(u);
}
__device__ __forceinline__ void mma8(float c[4], const unsigned a[4], const unsigned b[2]) {
    asm("mma.sync.aligned.m16n8k8.row.col.f32.tf32.tf32.f32 "
        "{%0,%1,%2,%3},{%4,%5,%6,%7},{%8,%9},{%0,%1,%2,%3};"
        : "+f"(c[0]), "+f"(c[1]), "+f"(c[2]), "+f"(c[3])
        : "r"(a[0]), "r"(a[1]), "r"(a[2]), "r"(a[3]), "r"(b[0]), "r"(b[1]));
}
__device__ __forceinline__ unsigned sptr(const void* p) {
    return (unsigned)__cvta_generic_to_shared(p);
}
__device__ __forceinline__ void cpa16(unsigned s, const void* g) {
    asm volatile("cp.async.cg.shared.global [%0], [%1], 16;\n" :: "r"(s), "l"(g));
}
#define CPA_COMMIT() asm volatile("cp.async.commit_group;\n" ::)
#define CPA_WAIT(n)  asm volatile("cp.async.wait_group %0;\n" :: "n"(n))

// ---------------- mask dtype classifier ----------------
__global__ void detect_mask_kernel(const unsigned int* __restrict__ mask) {
    __shared__ int has_f, has_big;
    if (threadIdx.x == 0) { has_f = 0; has_big = 0; }
    __syncthreads();
    #pragma unroll
    for (int u = 0; u < 4; u++) {
        unsigned int w = mask[threadIdx.x * 4 + u];
        if (w == 0x3F800000u) atomicOr(&has_f, 1);
        else if (w > 1u)      atomicOr(&has_big, 1);
    }
    __syncthreads();
    if (threadIdx.x == 0)
        g_mask_byte_mode = (!has_f && has_big) ? 1 : 0;
}

// ============ QKV projections: 128x128 tile, 3-stage cp.async, single-pass tf32 ============
// outputs pre-rounded to tf32 (consumer rounds anyway -> bitwise identical downstream)
#define APAD 20
#define BPAD 136
#define NKT (FF / 16)       // 64

__global__ __launch_bounds__(256) void proj_tf32_kernel(
    const float* __restrict__ q_in, const float* __restrict__ k_in,
    const float* __restrict__ v_in,
    const float* __restrict__ Wq, const float* __restrict__ bq,
    const float* __restrict__ Wk, const float* __restrict__ bk,
    const float* __restrict__ Wv, const float* __restrict__ bv)
{
    const float *A, *W, *bias; float *C;
    if (blockIdx.z == 0)      { A = q_in; W = Wq; bias = bq; C = g_q; }
    else if (blockIdx.z == 1) { A = k_in; W = Wk; bias = bk; C = g_k; }
    else                      { A = v_in; W = Wv; bias = bv; C = g_v; }

    __shared__ float As[3][128][APAD];
    __shared__ float Bs[3][16][BPAD];

    int tid = threadIdx.x, lane = tid & 31, warp = tid >> 5;
    int wm = (warp >> 2) * 64, wn = (warp & 3) * 32;
    int bm = blockIdx.y * 128, bn = blockIdx.x * 128;

    int ar = tid >> 2, ac = (tid & 3) * 4;
    int br = tid >> 5, bc = (tid & 31) * 4;

    float acc[4][4][4];
    #pragma unroll
    for (int i = 0; i < 4; i++)
        #pragma unroll
        for (int j = 0; j < 4; j++)
            #pragma unroll
            for (int r = 0; r < 4; r++) acc[i][j][r] = 0.f;

    auto load_stage = [&](int s, int t) {
        int k0 = t * 16;
        cpa16(sptr(&As[s][ar][ac]),      A + (size_t)(bm + ar)      * FF + k0 + ac);
        cpa16(sptr(&As[s][ar + 64][ac]), A + (size_t)(bm + ar + 64) * FF + k0 + ac);
        cpa16(sptr(&Bs[s][br][bc]),      W + (size_t)(k0 + br)     * FF + bn + bc);
        cpa16(sptr(&Bs[s][br + 8][bc]),  W + (size_t)(k0 + br + 8) * FF + bn + bc);
        CPA_COMMIT();
    };

    load_stage(0, 0);
    load_stage(1, 1);

    for (int t = 0; t < NKT; t++) {
        if (t + 1 < NKT) { CPA_WAIT(1); } else { CPA_WAIT(0); }
        __syncthreads();
        if (t + 2 < NKT) load_stage((t + 2) % 3, t + 2);

        int s = t % 3;
        #pragma unroll
        for (int ks = 0; ks < 16; ks += 8) {
            unsigned ah[4][4], bh[4][2];
            #pragma unroll
            for (int mt = 0; mt < 4; mt++) {
                int r = wm + mt * 16 + (lane >> 2);
                int k = ks + (lane & 3);
                ah[mt][0] = rnt(As[s][r][k]);
                ah[mt][1] = rnt(As[s][r + 8][k]);
                ah[mt][2] = rnt(As[s][r][k + 4]);
                ah[mt][3] = rnt(As[s][r + 8][k + 4]);
            }
            #pragma unroll
            for (int nt = 0; nt < 4; nt++) {
                int k = ks + (lane & 3);
                int n = wn + nt * 8 + (lane >> 2);
                bh[nt][0] = rnt(Bs[s][k][n]);
                bh[nt][1] = rnt(Bs[s][k + 4][n]);
            }
            #pragma unroll
            for (int mt = 0; mt < 4; mt++)
                #pragma unroll
                for (int nt = 0; nt < 4; nt++)
                    mma8(acc[mt][nt], ah[mt], bh[nt]);
        }
    }

    #pragma unroll
    for (int mt = 0; mt < 4; mt++) {
        int r = bm + wm + mt * 16 + (lane >> 2);
        #pragma unroll
        for (int nt = 0; nt < 4; nt++) {
            int cc = bn + wn + nt * 8 + 2 * (lane & 3);
            float b0 = bias[cc], b1 = bias[cc + 1];
            float2 o0 = make_float2(tfr(acc[mt][nt][0] + b0), tfr(acc[mt][nt][1] + b1));
            float2 o1 = make_float2(tfr(acc[mt][nt][2] + b0), tfr(acc[mt][nt][3] + b1));
            *(float2*)(C + (size_t)r * FF + cc)       = o0;
            *(float2*)(C + (size_t)(r + 8) * FF + cc) = o1;
        }
    }
}

// ---------------- fused attention: inputs pre-rounded (no IADD on Q/K/V frags),
//                  coalesced attn writes, vector mask loads ----------------
#define EPAD 68
#define ATT_SMEM ((4 * 64 * EPAD + 128) * 4)
__global__ __launch_bounds__(256) void attn_fused_kernel(
    float* __restrict__ attn, const unsigned int* __restrict__ mask,
    const float* __restrict__ qmask)
{
    extern __shared__ float sm[];
    float* Qs   = sm;
    float* Ks   = Qs + 64 * EPAD;
    float* Vs   = Ks + 64 * EPAD;
    float* Es   = Vs + 64 * EPAD;
    float* lsum = Es + 64 * EPAD;
    float* scs  = lsum + 64;

    int tid = threadIdx.x, lane = tid & 31, warp = tid >> 5;
    int hb = blockIdx.y, h = hb >> 2, b = hb & 3;
    int i0 = blockIdx.x * 64;
    int wm = (warp >> 2) * 32, wn = (warp & 3) * 16;
    int bytemode = g_mask_byte_mode;

    // Q tile (pre-rounded in gmem)
    #pragma unroll
    for (int u = 0; u < 2; u++) {
        int s = tid + u * 256;
        int r = s >> 3, c4 = (s & 7) * 8;
        float4 q0 = *(const float4*)(g_q + (size_t)(b * TT + i0 + r) * FF + h * DD + c4);
        float4 q1 = *(const float4*)(g_q + (size_t)(b * TT + i0 + r) * FF + h * DD + c4 + 4);
        *(float4*)&Qs[r * EPAD + c4]     = q0;
        *(float4*)&Qs[r * EPAD + c4 + 4] = q1;
    }
    if (tid < 64) lsum[tid] = 0.f;

    float X[2][2][4];
    #pragma unroll
    for (int i = 0; i < 2; i++)
        #pragma unroll
        for (int j = 0; j < 2; j++)
            #pragma unroll
            for (int r = 0; r < 4; r++) X[i][j][r] = 0.f;

    __syncthreads();

    for (int j0 = 0; j0 < TT; j0 += 64) {
        #pragma unroll
        for (int u = 0; u < 2; u++) {
            int s = tid + u * 256;
            int r = s >> 3, c4 = (s & 7) * 8;
            float4 k0 = *(const float4*)(g_k + (size_t)(b * TT + j0 + r) * FF + h * DD + c4);
            float4 k1 = *(const float4*)(g_k + (size_t)(b * TT + j0 + r) * FF + h * DD + c4 + 4);
            *(float4*)&Ks[r * EPAD + c4]     = k0;
            *(float4*)&Ks[r * EPAD + c4 + 4] = k1;
            float4 v0 = *(const float4*)(g_v + (size_t)(b * TT + j0 + r) * FF + h * DD + c4);
            float4 v1 = *(const float4*)(g_v + (size_t)(b * TT + j0 + r) * FF + h * DD + c4 + 4);
            *(float4*)&Vs[r * EPAD + c4]     = v0;
            *(float4*)&Vs[r * EPAD + c4 + 4] = v1;
        }
        __syncthreads();

        float sacc[2][2][4];
        #pragma unroll
        for (int i = 0; i < 2; i++)
            #pragma unroll
            for (int j = 0; j < 2; j++)
                #pragma unroll
                for (int r = 0; r < 4; r++) sacc[i][j][r] = 0.f;

        #pragma unroll
        for (int ks = 0; ks < 64; ks += 8) {
            unsigned ah[2][4], bh[2][2];
            #pragma unroll
            for (int mt = 0; mt < 2; mt++) {
                int r = wm + mt * 16 + (lane >> 2);
                int k = ks + (lane & 3);
                ah[mt][0] = __float_as_uint(Qs[r * EPAD + k]);
                ah[mt][1] = __float_as_uint(Qs[(r + 8) * EPAD + k]);
                ah[mt][2] = __float_as_uint(Qs[r * EPAD + k + 4]);
                ah[mt][3] = __float_as_uint(Qs[(r + 8) * EPAD + k + 4]);
            }
            #pragma unroll
            for (int nt = 0; nt < 2; nt++) {
                int n = wn + nt * 8 + (lane >> 2);
                int k = ks + (lane & 3);
                bh[nt][0] = __float_as_uint(Ks[n * EPAD + k]);
                bh[nt][1] = __float_as_uint(Ks[n * EPAD + k + 4]);
            }
            #pragma unroll
            for (int mt = 0; mt < 2; mt++)
                #pragma unroll
                for (int nt = 0; nt < 2; nt++)
                    mma8(sacc[mt][nt], ah[mt], bh[nt]);
        }

        // mask + exp -> Es (smem only; gmem write deferred to coalesced copy)
        #pragma unroll
        for (int mt = 0; mt < 2; mt++) {
            #pragma unroll
            for (int nt = 0; nt < 2; nt++) {
                int ri = wm + mt * 16 + (lane >> 2);
                int cj = wn + nt * 8 + 2 * (lane & 3);
                size_t gi0 = ((size_t)hb * TT + i0 + ri) * TT + j0 + cj;
                size_t gi1 = gi0 + (size_t)8 * TT;
                unsigned m00, m01, m10, m11;
                if (bytemode) {
                    const unsigned char* mb = (const unsigned char*)mask;
                    uchar2 c0 = *(const uchar2*)(mb + gi0);
                    uchar2 c1 = *(const uchar2*)(mb + gi1);
                    m00 = c0.x; m01 = c0.y; m10 = c1.x; m11 = c1.y;
                } else {
                    uint2 w0 = *(const uint2*)(mask + gi0);
                    uint2 w1 = *(const uint2*)(mask + gi1);
                    m00 = w0.x; m01 = w0.y; m10 = w1.x; m11 = w1.y;
                }
                Es[ri * EPAD + cj]           = m00 ? 0.f : __expf(sacc[mt][nt][0] * 0.125f);
                Es[ri * EPAD + cj + 1]       = m01 ? 0.f : __expf(sacc[mt][nt][1] * 0.125f);
                Es[(ri + 8) * EPAD + cj]     = m10 ? 0.f : __expf(sacc[mt][nt][2] * 0.125f);
                Es[(ri + 8) * EPAD + cj + 1] = m11 ? 0.f : __expf(sacc[mt][nt][3] * 0.125f);
            }
        }
        __syncthreads();

        // coalesced unnormalized attn write from Es
        #pragma unroll
        for (int u = 0; u < 4; u++) {
            int s2 = tid + u * 256;
            int r = s2 >> 4, c4 = (s2 & 15) * 4;
            *(float4*)(attn + ((size_t)hb * TT + i0 + r) * TT + j0 + c4) =
                *(const float4*)&Es[r * EPAD + c4];
        }

        // row sums
        {
            int r = tid >> 2, seg = (tid & 3) * 16;
            float p = 0.f;
            #pragma unroll
            for (int t = 0; t < 16; t++) p += Es[r * EPAD + seg + t];
            p += __shfl_xor_sync(0xFFFFFFFFu, p, 1);
            p += __shfl_xor_sync(0xFFFFFFFFu, p, 2);
            if ((tid & 3) == 0) lsum[r] += p;
        }

        // X += E @ V  (E needs rounding; V pre-rounded)
        #pragma unroll
        for (int ks = 0; ks < 64; ks += 8) {
            unsigned ae[2][4], bv[2][2];
            #pragma unroll
            for (int mt = 0; mt < 2; mt++) {
                int r = wm + mt * 16 + (lane >> 2);
                int k = ks + (lane & 3);
                ae[mt][0] = rnt(Es[r * EPAD + k]);
                ae[mt][1] = rnt(Es[(r + 8) * EPAD + k]);
                ae[mt][2] = rnt(Es[r * EPAD + k + 4]);
                ae[mt][3] = rnt(Es[(r + 8) * EPAD + k + 4]);
            }
            #pragma unroll
            for (int nt = 0; nt < 2; nt++) {
                int n = wn + nt * 8 + (lane >> 2);
                int k = ks + (lane & 3);
                bv[nt][0] = __float_as_uint(Vs[k * EPAD + n]);
                bv[nt][1] = __float_as_uint(Vs[(k + 4) * EPAD + n]);
            }
            #pragma unroll
            for (int mt = 0; mt < 2; mt++)
                #pragma unroll
                for (int nt = 0; nt < 2; nt++)
                    mma8(X[mt][nt], ae[mt], bv[nt]);
        }
        __syncthreads();
    }

    if (tid < 64) scs[tid] = qmask[b * TT + i0 + tid] / lsum[tid];
    __syncthreads();

    // x epilogue: pre-round to tf32 (final rounds anyway -> bitwise identical)
    #pragma unroll
    for (int mt = 0; mt < 2; mt++) {
        int ri = wm + mt * 16 + (lane >> 2);
        float sc0 = scs[ri];
        float sc1 = scs[ri + 8];
        #pragma unroll
        for (int nt = 0; nt < 2; nt++) {
            int d = wn + nt * 8 + 2 * (lane & 3);
            float2 o0 = make_float2(tfr(X[mt][nt][0] * sc0), tfr(X[mt][nt][1] * sc0));
            float2 o1 = make_float2(tfr(X[mt][nt][2] * sc1), tfr(X[mt][nt][3] * sc1));
            *(float2*)(g_x + (size_t)(b * TT + i0 + ri) * FF + h * DD + d)     = o0;
            *(float2*)(g_x + (size_t)(b * TT + i0 + ri + 8) * FF + h * DD + d) = o1;
        }
    }

    // normalize the CTA's own attn block in place (L2-hot)
    for (int u = 0; u < 64; u++) {
        int s = tid + u * 256;
        int r = s >> 8, c4 = (s & 255) << 2;
        float sc = scs[r];
        float4* p = (float4*)(attn + ((size_t)hb * TT + i0 + r) * TT + c4);
        float4 v = *p;
        v.x *= sc; v.y *= sc; v.z *= sc; v.w *= sc;
        *p = v;
    }
}

// ============ final: 128x128 tile, 3-stage cp.async, unconditional rnt (R9 inner loop) ============
#define FNKT (2 * FF / 16)    // 128
__global__ __launch_bounds__(256) void final_tf32_kernel(
    const float* __restrict__ query, const float* __restrict__ Wf,
    const float* __restrict__ bf, float* __restrict__ out)
{
    __shared__ float As[3][128][APAD];
    __shared__ float Bs[3][16][BPAD];

    int tid = threadIdx.x, lane = tid & 31, warp = tid >> 5;
    int wm = (warp >> 2) * 64, wn = (warp & 3) * 32;
    int bm = blockIdx.y * 128, bn = blockIdx.x * 128;

    int ar = tid >> 2, ac = (tid & 3) * 4;
    int br = tid >> 5, bc = (tid & 31) * 4;

    float acc[4][4][4];
    #pragma unroll
    for (int i = 0; i < 4; i++)
        #pragma unroll
        for (int j = 0; j < 4; j++)
            #pragma unroll
            for (int r = 0; r < 4; r++) acc[i][j][r] = 0.f;

    auto load_stage = [&](int s, int t) {
        int k0 = t * 16;
        const float* a_base;
        int koff;
        if (k0 < FF) { a_base = g_x;   koff = k0; }
        else         { a_base = query; koff = k0 - FF; }
        cpa16(sptr(&As[s][ar][ac]),      a_base + (size_t)(bm + ar)      * FF + koff + ac);
        cpa16(sptr(&As[s][ar + 64][ac]), a_base + (size_t)(bm + ar + 64) * FF + koff + ac);
        cpa16(sptr(&Bs[s][br][bc]),      Wf + (size_t)(k0 + br)     * FF + bn + bc);
        cpa16(sptr(&Bs[s][br + 8][bc]),  Wf + (size_t)(k0 + br + 8) * FF + bn + bc);
        CPA_COMMIT();
    };

    load_stage(0, 0);
    load_stage(1, 1);

    for (int t = 0; t < FNKT; t++) {
        if (t + 1 < FNKT) { CPA_WAIT(1); } else { CPA_WAIT(0); }
        __syncthreads();
        if (t + 2 < FNKT) load_stage((t + 2) % 3, t + 2);

        int s = t % 3;
        #pragma unroll
        for (int ks = 0; ks < 16; ks += 8) {
            unsigned ah[4][4], bh[4][2];
            #pragma unroll
            for (int mt = 0; mt < 4; mt++) {
                int r = wm + mt * 16 + (lane >> 2);
                int k = ks + (lane & 3);
                ah[mt][0] = rnt(As[s][r][k]);
                ah[mt][1] = rnt(As[s][r + 8][k]);
                ah[mt][2] = rnt(As[s][r][k + 4]);
                ah[mt][3] = rnt(As[s][r + 8][k + 4]);
            }
            #pragma unroll
            for (int nt = 0; nt < 4; nt++) {
                int k = ks + (lane & 3);
                int n = wn + nt * 8 + (lane >> 2);
                bh[nt][0] = rnt(Bs[s][k][n]);
                bh[nt][1] = rnt(Bs[s][k + 4][n]);
            }
            #pragma unroll
            for (int mt = 0; mt < 4; mt++)
                #pragma unroll
                for (int nt = 0; nt < 4; nt++)
                    mma8(acc[mt][nt], ah[mt], bh[nt]);
        }
    }

    #pragma unroll
    for (int mt = 0; mt < 4; mt++) {
        int r = bm + wm + mt * 16 + (lane >> 2);
        #pragma unroll
        for (int nt = 0; nt < 4; nt++) {
            int cc = bn + wn + nt * 8 + 2 * (lane & 3);
            float b0 = bf[cc], b1 = bf[cc + 1];
            const float* q0 = query + (size_t)r * FF + cc;
            const float* q1 = query + (size_t)(r + 8) * FF + cc;
            float2 o0 = make_float2(acc[mt][nt][0] + b0 + q0[0],
                                    acc[mt][nt][1] + b1 + q0[1]);
            float2 o1 = make_float2(acc[mt][nt][2] + b0 + q1[0],
                                    acc[mt][nt][3] + b1 + q1[1]);
            *(float2*)(out + (size_t)r * FF + cc)       = o0;
            *(float2*)(out + (size_t)(r + 8) * FF + cc) = o1;
        }
    }
}

// ---------------- launch ----------------
extern "C" void kernel_launch(void* const* d_in, const int* in_sizes, int n_in,
                              void* d_out, int out_size)
{
    const float* query = (const float*)d_in[0];
    const float* key   = (const float*)d_in[1];
    const float* value = (const float*)d_in[2];
    const unsigned int* mask = (const unsigned int*)d_in[3];
    const float* qmask = (const float*)d_in[4];
    const float* Wq = (const float*)d_in[5];
    const float* bq = (const float*)d_in[6];
    const float* Wk = (const float*)d_in[7];
    const float* bk = (const float*)d_in[8];
    const float* Wv = (const float*)d_in[9];
    const float* bv = (const float*)d_in[10];
    const float* Wf = (const float*)d_in[11];
    const float* bf = (const float*)d_in[12];

    float* out  = (float*)d_out;
    float* attn = out + (size_t)NR * FF;

    cudaFuncSetAttribute(attn_fused_kernel,
                         cudaFuncAttributeMaxDynamicSharedMemorySize, ATT_SMEM);

    detect_mask_kernel<<<1, 256>>>(mask);
    proj_tf32_kernel<<<dim3(8, 32, 3), 256>>>(query, key, value, Wq, bq, Wk, bk, Wv, bv);
    attn_fused_kernel<<<dim3(16, 64), 256, ATT_SMEM>>>(attn, mask, qmask);
    final_tf32_kernel<<<dim3(8, 32), 256>>>(query, Wf, bf, out);
}